// round 17
// baseline (speedup 1.0000x reference)
#include <cuda_runtime.h>
#include <cuda_fp16.h>
#include <cstdint>

// ---------------------------------------------------------------------------
// Problem constants
// ---------------------------------------------------------------------------
#define NC      100     // NUM_CLASSES
#define DDIM    512     // feature dim
#define SSPEC   10      // specialists
#define KCLUS   10      // cluster size
#define NPAD    104     // padded N (13 x n8 tiles)
#define NTILES  13
#define TILE_M  128
#define KC      64      // K per chunk
#define NCHUNK  (DDIM / KC)   // 8
#define THREADS 256

// SMEM: 1KB hdr + 8 warps x 2 x 4KB fp32 staging + 8 warps x 2 x 2KB A tile
#define STG_OFF   1024
#define A_REGION  (1024 + 65536)
#define SMEM_DYN  (1024 + 65536 + 32768)   // 99328, 2 CTAs/SM

// ---------------------------------------------------------------------------
// Device scratch
// ---------------------------------------------------------------------------
__device__ __align__(16) float g_b1[NC];
__device__ __align__(16) float g_beff[NPAD];
__device__ int g_cls_s[NC];
__device__ int g_cls_k[NC];
// B fragments, single fp16 plane, native m16n8k16 per-lane layout:
// [ks 0..31][nt 0..12][lane 0..31] -> uint2 {b0, b1}
__device__ __align__(16) uint2 g_Bfrag[32 * NTILES * 32];

// ---------------------------------------------------------------------------
// Helpers
// ---------------------------------------------------------------------------
__device__ __forceinline__ uint32_t cvta_smem(const void* p) {
    return (uint32_t)__cvta_generic_to_shared(p);
}
__device__ __forceinline__ uint32_t sw128(uint32_t off) {
    return off ^ ((off >> 3) & 0x70);
}
__device__ __forceinline__ void cp_async16(uint32_t dst, const void* src) {
    asm volatile("cp.async.cg.shared.global [%0], [%1], 16;" :: "r"(dst), "l"(src));
}
__device__ __forceinline__ void ldmatrix_x4(uint32_t* r, uint32_t addr) {
    asm volatile("ldmatrix.sync.aligned.m8n8.x4.shared.b16 {%0,%1,%2,%3}, [%4];"
                 : "=r"(r[0]), "=r"(r[1]), "=r"(r[2]), "=r"(r[3]) : "r"(addr));
}
__device__ __forceinline__ void mma_f16(float* d, const uint32_t* a, uint2 b) {
    asm volatile(
        "mma.sync.aligned.m16n8k16.row.col.f32.f16.f16.f32 "
        "{%0,%1,%2,%3}, {%4,%5,%6,%7}, {%8,%9}, {%0,%1,%2,%3};"
        : "+f"(d[0]), "+f"(d[1]), "+f"(d[2]), "+f"(d[3])
        : "r"(a[0]), "r"(a[1]), "r"(a[2]), "r"(a[3]), "r"(b.x), "r"(b.y));
}

// ---------------------------------------------------------------------------
// prepA: cluster map + folded first-layer bias g_b1
// ---------------------------------------------------------------------------
__global__ void prepA_kernel(const int* __restrict__ clusters,
                             const float* __restrict__ bg,
                             const float* __restrict__ bs) {
    int t = threadIdx.x;
    if (t < NC) {
        int s = t / KCLUS, k = t % KCLUS;
        int c = clusters[t];
        g_cls_s[c] = s;
        g_cls_k[c] = k;
    }
    __syncthreads();
    if (t < NC) {
        int s = g_cls_s[t], k = g_cls_k[t];
        float bsum = 0.f;
        #pragma unroll
        for (int sp = 0; sp < SSPEC; sp++) bsum += bs[sp * (KCLUS + 1) + KCLUS];
        g_b1[t] = bg[t] + bs[s * (KCLUS + 1) + k] +
                  (bsum - bs[s * (KCLUS + 1) + KCLUS]) * (1.0f / (NC - KCLUS));
    }
}

// ---------------------------------------------------------------------------
// prepC (fused): fold W1[d][:] on the fly, then Weff[d][n] = W1[d]·Wc[:,n],
// stored as fp16 directly into the mma fragment image.
// 512 blocks (d) x 104 threads (n).
// ---------------------------------------------------------------------------
__global__ void prepC_kernel(const float* __restrict__ Wg,
                             const float* __restrict__ Ws,
                             const float* __restrict__ Wc) {
    __shared__ float w1row[NC];
    int d = blockIdx.x;
    int n = threadIdx.x;

    float dsum = 0.f;
    #pragma unroll
    for (int sp = 0; sp < SSPEC; sp++)
        dsum += Ws[sp * DDIM * (KCLUS + 1) + d * (KCLUS + 1) + KCLUS];
    if (n < NC) {
        int s = g_cls_s[n], k = g_cls_k[n];
        w1row[n] = Wg[d * NC + n] + Ws[s * DDIM * (KCLUS + 1) + d * (KCLUS + 1) + k] +
                   (dsum - Ws[s * DDIM * (KCLUS + 1) + d * (KCLUS + 1) + KCLUS]) *
                       (1.0f / (NC - KCLUS));
    }
    __syncthreads();

    float acc = 0.f;
    if (n < NC) {
        #pragma unroll 4
        for (int t = 0; t < NC; t++)
            acc += w1row[t] * Wc[t * NC + n];
    }
    // fragment index for element (d, n):
    //   ks = d>>4, r = d&15, reg = r>>3, lane = (n&7)*4 + ((r&7)>>1), par = d&1
    int ks = d >> 4, r = d & 15;
    int lane = ((n & 7) << 2) | ((r & 7) >> 1);
    int idx = (((ks * NTILES + (n >> 3)) * 32 + lane) << 2) | ((r >> 3) << 1) | (d & 1);
    unsigned short* bu = (unsigned short*)g_Bfrag;
    bu[idx] = __half_as_ushort(__float2half_rn(acc));
}

// ---------------------------------------------------------------------------
// prepD: beff = b1 @ Wc + bc  (one block per output col, warp-parallel dot)
// ---------------------------------------------------------------------------
__global__ void prepD_kernel(const float* __restrict__ Wc,
                             const float* __restrict__ bc) {
    int c = blockIdx.x;
    int lane = threadIdx.x;
    float s = 0.f;
    if (c < NC) {
        #pragma unroll
        for (int k = lane; k < NC; k += 32)
            s += g_b1[k] * Wc[k * NC + c];
    }
    #pragma unroll
    for (int o = 16; o > 0; o >>= 1)
        s += __shfl_xor_sync(0xFFFFFFFFu, s, o);
    if (lane == 0)
        g_beff[c] = (c < NC) ? (s + bc[c]) : 0.f;
}

// ---------------------------------------------------------------------------
// Main GEMM: out = relu(x @ Weff + beff), fp16 mma.sync, single W plane.
// R16: barrier-free warp-autonomous pipeline. Each of 8 warps owns a private
// m16 row slice (rows w*16..w*16+15) with its own double-buffered fp32
// staging (2x4KB) and fp16 A tile (2x2KB): stage -> convert -> ldmatrix ->
// MMA over all 13 n-tiles, no __syncthreads anywhere in the loop. All WAR
// hazards are warp-program-order; cp.async groups are per-thread. 16 warps/SM
// free-run and self-stagger (generalizes the R15 anti-phase win from 2 CTA
// phases to 16 warp phases). CTA chunk rotation kept for DRAM spread.
// ---------------------------------------------------------------------------
__global__ __launch_bounds__(THREADS, 2)
void gemm_main_kernel(const float* __restrict__ x, float* __restrict__ out) {
    extern __shared__ unsigned char smem_raw[];
    uint32_t sb0 = cvta_smem(smem_raw);
    uint32_t sb = (sb0 + 1023u) & ~1023u;
    unsigned char* smem = smem_raw + (sb - sb0);

    const int tid  = threadIdx.x;
    const int wid  = tid >> 5;
    const int lane = tid & 31;

    // warp-private regions
    const uint32_t WSTG = sb + STG_OFF + (uint32_t)wid * 8192;       // 2 x 4KB
    float* wstg = (float*)(smem + STG_OFF + wid * 8192);
    const uint32_t WA = sb + A_REGION + (uint32_t)wid * 4096;        // 2 x 2KB
    unsigned char* wa = smem + A_REGION + wid * 4096;

    const int rot = blockIdx.x & 7;         // per-CTA chunk-order rotation

    // per-thread staging coordinates: slot = lane + 32*i -> r = slot>>4, q = slot&15
    // warp owns global rows bid*128 + wid*16 + r
    const float* xwarp = x + ((size_t)blockIdx.x * TILE_M + wid * 16) * DDIM;

    float acc[NTILES][4];
    #pragma unroll
    for (int j = 0; j < NTILES; j++)
        #pragma unroll
        for (int qq = 0; qq < 4; qq++) acc[j][qq] = 0.f;

    // prologue: stage physical chunk rot (logical 0) into buf 0
    #pragma unroll
    for (int i = 0; i < 8; i++) {
        int slot = lane + 32 * i;
        int r = slot >> 4, q = slot & 15;
        cp_async16(WSTG + (uint32_t)(r * 64 + q * 4) * 4,
                   xwarp + (size_t)r * DDIM + rot * KC + q * 4);
    }
    asm volatile("cp.async.commit_group;" ::: "memory");

    for (int ch = 0; ch < NCHUNK; ch++) {
        const int mc = (ch + rot) & 7;      // mapped (physical) chunk

        // issue staging for ch+1 (warp-private buffer (ch+1)&1)
        if (ch + 1 < NCHUNK) {
            const int mn = (ch + 1 + rot) & 7;
            uint32_t bufoff = (uint32_t)((ch + 1) & 1) * 4096;
            #pragma unroll
            for (int i = 0; i < 8; i++) {
                int slot = lane + 32 * i;
                int r = slot >> 4, q = slot & 15;
                cp_async16(WSTG + bufoff + (uint32_t)(r * 64 + q * 4) * 4,
                           xwarp + (size_t)r * DDIM + mn * KC + q * 4);
            }
            asm volatile("cp.async.commit_group;" ::: "memory");
            asm volatile("cp.async.wait_group 1;" ::: "memory");
        } else {
            asm volatile("cp.async.wait_group 0;" ::: "memory");
        }

        // convert staged fp32 -> fp16 into warp A buffer ch&1.
        // WAR vs ldmatrix(ch-2) on the same buffer is warp-program-order.
        const float* xb = wstg + (ch & 1) * 1024;
        unsigned char* ab = wa + (ch & 1) * 2048;
        #pragma unroll
        for (int i = 0; i < 8; i++) {
            int slot = lane + 32 * i;
            int r = slot >> 4, q = slot & 15;
            float4 v = *(const float4*)(xb + r * 64 + q * 4);
            __half2 p01 = __floats2half2_rn(v.x, v.y);
            __half2 p23 = __floats2half2_rn(v.z, v.w);
            uint32_t off = sw128((uint32_t)(r * 128 + q * 8));
            *(uint2*)(ab + off) = make_uint2(*(uint32_t*)&p01, *(uint32_t*)&p23);
        }
        __syncwarp();   // converts visible warp-wide before ldmatrix

        // MMA over 4 k16 steps, full 13 n-tiles
        const uint32_t AT = WA + (uint32_t)(ch & 1) * 2048;
        #pragma unroll
        for (int ks = 0; ks < 4; ks++) {
            uint32_t a[4];
            uint32_t off = sw128((uint32_t)((lane & 15) * 128 + ks * 32 + (lane >> 4) * 16));
            ldmatrix_x4(a, AT + off);
            const int gks = mc * 4 + ks;
            const uint2* bp = g_Bfrag + (size_t)(gks * NTILES) * 32 + lane;
            #pragma unroll
            for (int j = 0; j < NTILES; j++) {
                uint2 b = bp[j * 32];
                mma_f16(acc[j], a, b);
            }
        }
    }

    // ---- epilogue: bias + relu + direct STG ----
    const int g  = lane >> 2;
    const int tq = lane & 3;
    const int mrow = blockIdx.x * TILE_M + wid * 16;
    #pragma unroll
    for (int j = 0; j < NTILES; j++) {
        int c = j * 8 + tq * 2;
        if (c < NC) {
            float2 bv = *(const float2*)&g_beff[c];
            int r0 = mrow + g;
            float v0 = acc[j][0] + bv.x;
            float v1 = acc[j][1] + bv.y;
            float v2 = acc[j][2] + bv.x;
            float v3 = acc[j][3] + bv.y;
            float2 o0 = make_float2(v0 > 0.f ? v0 : 0.f, v1 > 0.f ? v1 : 0.f);
            float2 o1 = make_float2(v2 > 0.f ? v2 : 0.f, v3 > 0.f ? v3 : 0.f);
            *(float2*)(out + (size_t)r0 * NC + c)       = o0;
            *(float2*)(out + (size_t)(r0 + 8) * NC + c) = o1;
        }
    }
}

// ---------------------------------------------------------------------------
// Launch
// ---------------------------------------------------------------------------
extern "C" void kernel_launch(void* const* d_in, const int* in_sizes, int n_in,
                              void* d_out, int out_size) {
    const float* x        = (const float*)d_in[0];
    const float* Wg       = (const float*)d_in[1];
    const float* bg       = (const float*)d_in[2];
    const float* Ws       = (const float*)d_in[3];
    const float* bs       = (const float*)d_in[4];
    const float* Wc       = (const float*)d_in[5];
    const float* bc       = (const float*)d_in[6];
    const int*   clusters = (const int*)d_in[7];
    float* out = (float*)d_out;

    int Btot = in_sizes[0] / DDIM;      // 131072
    int grid = Btot / TILE_M;           // 1024

    cudaFuncSetAttribute(gemm_main_kernel,
                         cudaFuncAttributeMaxDynamicSharedMemorySize, SMEM_DYN);

    prepA_kernel<<<1, 128>>>(clusters, bg, bs);
    prepD_kernel<<<NPAD, 32>>>(Wc, bc);
    prepC_kernel<<<DDIM, NPAD>>>(Wg, Ws, Wc);
    gemm_main_kernel<<<grid, THREADS, SMEM_DYN>>>(x, out);
}